// round 15
// baseline (speedup 1.0000x reference)
#include <cuda_runtime.h>
#include <math.h>

#define NCTA 128
#define NT 512
#define Bz 128
#define Lz 1024
#define Dz 256
#define Tz 32
#define BD (Bz*Dz)      /* 32768 */
#define SAS 516

// smem layout (float offsets)
#define OFF_WR 0        /* 32x516 = 16512 */
#define OFF_WW 16512
#define OFF_WC 33024    /* 8x516 = 4128 */
#define OFF_A  37152    /* 32x516 = 16512 (also partial buffer) */
#define OFF_Z  53664    /* 1024 */
#define OFF_HR 54688    /* 256 */
#define OFF_HW 54944    /* 256 */
#define OFF_RED 55200   /* 32 */
#define OFF_MASK 55744  /* 1024 bytes */
#define SMEM_FLOATS 56000
#define SMEM_BYTES (SMEM_FLOATS*4)

// ---------------- scratch ----------------
__device__ __align__(16) float g_hr[2*BD];
__device__ __align__(16) float g_hw[2*BD];
__device__ __align__(16) float g_hrt[2*BD];     // tf32-rounded copies of hr
__device__ __align__(16) float g_hwt[2*BD];     // tf32-rounded copies of hw
__device__ __align__(16) float g_embt[Tz*BD];   // tf32-rounded emb (t>=1 used)
__device__ __align__(16) float g_m[BD];
__device__ __align__(16) float g_L1[BD];
__device__ __align__(16) float g_L2[BD];
__device__ __align__(16) float g_S[Bz];
__device__ __align__(16) float g_wcsum[Dz];
__device__ unsigned g_flags[NCTA*32];

// ---------------- helpers ----------------
__device__ __forceinline__ float warp_sum(float v){
#pragma unroll
  for (int o=16;o;o>>=1) v += __shfl_xor_sync(0xffffffffu,v,o);
  return v;
}
__device__ __forceinline__ float block_sum(float v, float* sbuf){
  v = warp_sum(v);
  int lane = threadIdx.x & 31, w = threadIdx.x >> 5;
  __syncthreads();
  if (lane == 0) sbuf[w] = v;
  __syncthreads();
  float r = sbuf[0];
#pragma unroll
  for (int i=1;i<16;i++) r += sbuf[i];
  return r;
}
__device__ __forceinline__ void block_sum2(float a, float b, float* sbuf,
                                           float& ra, float& rb){
  a = warp_sum(a); b = warp_sum(b);
  int lane = threadIdx.x & 31, w = threadIdx.x >> 5;
  __syncthreads();
  if (lane == 0) { sbuf[w] = a; sbuf[16 + w] = b; }
  __syncthreads();
  float xa = sbuf[0], xb = sbuf[16];
#pragma unroll
  for (int i=1;i<16;i++) { xa += sbuf[i]; xb += sbuf[16 + i]; }
  ra = xa; rb = xb;
}
__device__ __forceinline__ float block_max(float v, float* sbuf){
#pragma unroll
  for (int o=16;o;o>>=1) v = fmaxf(v, __shfl_xor_sync(0xffffffffu,v,o));
  int lane = threadIdx.x & 31, w = threadIdx.x >> 5;
  __syncthreads();
  if (lane == 0) sbuf[w] = v;
  __syncthreads();
  float r = sbuf[0];
#pragma unroll
  for (int i=1;i<16;i++) r = fmaxf(r, sbuf[i]);
  return r;
}
__device__ __forceinline__ float sigmf(float x){
  return __fdividef(1.f, 1.f + __expf(-x));
}
__device__ __forceinline__ float tanhff(float x){
  float e = __expf(2.f*x);
  return 1.f - __fdividef(2.f, e + 1.f);
}
__device__ __forceinline__ float tf32r(float x){
  unsigned u;
  asm("cvt.rna.tf32.f32 %0, %1;" : "=r"(u) : "f"(x));
  return __uint_as_float(u);
}
__device__ __forceinline__ float4 tf32r4(float4 v){
  v.x = tf32r(v.x); v.y = tf32r(v.y); v.z = tf32r(v.z); v.w = tf32r(v.w);
  return v;
}

// grid barrier split: arrive / wait (R7 flag pattern)
__device__ __forceinline__ void bar_arrive(unsigned gen){
  __syncthreads();
  if (threadIdx.x == 0) {
    __threadfence();
    *(volatile unsigned*)&g_flags[blockIdx.x*32] = gen;
  }
}
__device__ __forceinline__ void bar_wait(unsigned gen){
  if (threadIdx.x < NCTA) {
    while (*(volatile unsigned*)&g_flags[threadIdx.x*32] < gen) { }
  }
  __syncthreads();
  if (threadIdx.x == 0) __threadfence();
  __syncthreads();
}
__device__ __forceinline__ void grid_bar(unsigned gen){
  bar_arrive(gen);
  bar_wait(gen);
}

#define MMA_TF32(c0,c1,c2,c3,a0,a1,a2,a3,b0,b1) \
  asm volatile("mma.sync.aligned.m16n8k8.row.col.f32.tf32.tf32.f32 " \
    "{%0,%1,%2,%3}, {%4,%5,%6,%7}, {%8,%9}, {%0,%1,%2,%3};" \
    : "+f"(c0),"+f"(c1),"+f"(c2),"+f"(c3) \
    : "r"(a0),"r"(a1),"r"(a2),"r"(a3),"r"(b0),"r"(b1))

// LSTM GEMM via tf32 mma (16-warp): C[32b x 32j] = A[32x512]*W^T.
// 16 warps = mt(2) x ntt(2) x kh(4 k128). sP may alias sA.
// Direct 4-gate combine: pre[4] valid for tid<256. Trailing __syncthreads
// so callers may write sA immediately after return.
__device__ __forceinline__ void gemm_lstm(
    const float* sA, const float* sW, float* sP, int tid, float* pre)
{
  const int lane = tid & 31, w = tid >> 5;
  const int kh = w & 3, mt = (w >> 2) & 1, ntt = w >> 3;
  const int gid = lane >> 2, tig = lane & 3;
  const int m0 = mt << 4, n0 = ntt << 4;
  const int kb = kh << 7;
  const float* A0 = sA + (m0 + gid)*SAS + kb + tig;
  const float* A1 = A0 + 8*SAS;
  const float* B0 = sW + (n0 + gid)*SAS + kb + tig;
  const float* B1 = B0 + 8*SAS;

  float c00=0.f,c01=0.f,c02=0.f,c03=0.f;
  float c10=0.f,c11=0.f,c12=0.f,c13=0.f;
#pragma unroll
  for (int i = 0; i < 16; i++) {
    const int k = i << 3;
    unsigned a0 = __float_as_uint(A0[k]);
    unsigned a1 = __float_as_uint(A1[k]);
    unsigned a2 = __float_as_uint(A0[k+4]);
    unsigned a3 = __float_as_uint(A1[k+4]);
    unsigned b0 = __float_as_uint(B0[k]);
    unsigned b1 = __float_as_uint(B0[k+4]);
    unsigned b2 = __float_as_uint(B1[k]);
    unsigned b3 = __float_as_uint(B1[k+4]);
    MMA_TF32(c00,c01,c02,c03, a0,a1,a2,a3, b0,b1);
    MMA_TF32(c10,c11,c12,c13, a0,a1,a2,a3, b2,b3);
  }
  __syncthreads();               // all sA reads complete before overwrite
  {
    float* r0p = sP + ((kh<<5) + m0 + gid)*33 + n0 + (tig<<1);
    float* r1p = r0p + 8*33;
    r0p[0] = c00; r0p[1] = c01;
    r1p[0] = c02; r1p[1] = c03;
    r0p[8] = c10; r0p[9] = c11;
    r1p[8] = c12; r1p[9] = c13;
  }
  __syncthreads();
  if (tid < 256) {
    const int b_i = tid >> 3, d_i = tid & 7;
#pragma unroll
    for (int g = 0; g < 4; g++) {
      float s = 0.f;
#pragma unroll
      for (int q = 0; q < 4; q++) s += sP[((q<<5) + b_i)*33 + g*8 + d_i];
      pre[g] = s;
    }
  }
  __syncthreads();               // combine reads done before caller writes sA
}

// read-LSTM epoch: stage [x|h_in] (conv: apply tf32 rounding; else pure copy),
// gemm vs sWr, pointwise -> hr fp32 + tf32 copy.
__device__ __forceinline__ void epoch_read_lstm(
    float* sA, const float* sWr,
    const float* __restrict__ x, const float* __restrict__ h_in, int conv,
    float* __restrict__ hr_out, float* __restrict__ hrt_out,
    int tid, int gh, int b0, int b, int d,
    const float* br, float& cr_reg)
{
  const float4* X = (const float4*)x;
  const float4* H = (const float4*)h_in;
  float4* A4 = (float4*)sA;
  if (conv) {
    for (int idx = tid; idx < 4096; idx += NT) {
      int r = idx >> 7, c = idx & 127;
      float4 v = (c < 64) ? X[(size_t)(b0+r)*64 + c] : H[(size_t)(b0+r)*64 + (c-64)];
      A4[r*129 + c] = tf32r4(v);
    }
  } else {
    for (int idx = tid; idx < 4096; idx += NT) {
      int r = idx >> 7, c = idx & 127;
      float4 v = (c < 64) ? X[(size_t)(b0+r)*64 + c] : H[(size_t)(b0+r)*64 + (c-64)];
      A4[r*129 + c] = v;
    }
  }
  __syncthreads();
  float pre[4];
  gemm_lstm(sA, sWr, sA, tid, pre);
  if (gh == 0) {
    float ig = sigmf(pre[0] + br[0]);
    float fg = sigmf(pre[1] + br[1]);
    float gg = tanhff(pre[2] + br[2]);
    float og = sigmf(pre[3] + br[3]);
    cr_reg = fmaf(fg, cr_reg, ig*gg);
    float hv = og * tanhff(cr_reg);
    hr_out[b*Dz + d] = hv;
    hrt_out[b*Dz + d] = tf32r(hv);
  }
}

// ---------------- the persistent mega-kernel ----------------
__global__ __launch_bounds__(NT,1) void mega(
  const float* __restrict__ emb, const float* __restrict__ hr0,
  const float* __restrict__ cr0, const float* __restrict__ hw0,
  const float* __restrict__ cw0, const float* __restrict__ M,
  const int* __restrict__ mask,
  const float* __restrict__ Wih_r, const float* __restrict__ Whh_r,
  const float* __restrict__ bih_r, const float* __restrict__ bhh_r,
  const float* __restrict__ Wc,    const float* __restrict__ bc,
  const float* __restrict__ Wih_w, const float* __restrict__ Whh_w,
  const float* __restrict__ bih_w, const float* __restrict__ bhh_w,
  float* __restrict__ out)
{
  extern __shared__ __align__(16) float sm[];
  float* sWr = sm + OFF_WR;
  float* sWw = sm + OFF_WW;
  float* sWc = sm + OFF_WC;
  float* sA  = sm + OFF_A;
  float* sZ  = sm + OFF_Z;
  float* sHr = sm + OFF_HR;
  float* sHw = sm + OFF_HW;
  float* sRed = sm + OFF_RED;
  unsigned char* sMask = (unsigned char*)(sm + OFF_MASK);

  const int tid = threadIdx.x;
  const int cta = blockIdx.x;
  const int jb = cta >> 2;
  const int bb = cta & 3;
  const int b0 = bb << 5;
  const int d0 = jb << 3;
  const int cell = tid & 255;
  const int b_i = cell >> 3, d_i = cell & 7;
  const int gh = tid >> 8;
  const int b = b0 + b_i, d = d0 + d_i;
  const int bown = cta;
  unsigned bgen = 0;

  // ---- emb preconversion for t>=1 (ordered before A'(1) by grid_bar #1) ----
  {
    const float4* E4 = (const float4*)(emb + BD);
    float4* ET4 = (float4*)(g_embt + BD);
    const int per = ((Tz-1)*BD/4) / NCTA;   // 1984
    const int base = cta * per;
    for (int i = tid; i < per; i += NT) ET4[base + i] = tf32r4(E4[base + i]);
  }

  // ---- one-time staging ----
  {
    const float4* Wi = (const float4*)Wih_r;
    const float4* Wh = (const float4*)Whh_r;
    float4* W4 = (float4*)sWr;
    for (int idx = tid; idx < 4096; idx += NT) {
      int r = idx >> 7, c = idx & 127;
      int j = ((r >> 3) << 8) + d0 + (r & 7);
      float4 v = (c < 64) ? Wi[(size_t)j*64 + c] : Wh[(size_t)j*64 + (c-64)];
      W4[r*129 + c] = tf32r4(v);
    }
  }
  {
    const float4* Wi = (const float4*)Wih_w;
    const float4* Wh = (const float4*)Whh_w;
    float4* W4 = (float4*)sWw;
    for (int idx = tid; idx < 4096; idx += NT) {
      int r = idx >> 7, c = idx & 127;
      int j = ((r >> 3) << 8) + d0 + (r & 7);
      float4 v = (c < 64) ? Wi[(size_t)j*64 + c] : Wh[(size_t)j*64 + (c-64)];
      W4[r*129 + c] = tf32r4(v);
    }
  }
  {
    const float4* Wc4 = (const float4*)Wc;
    float4* W4 = (float4*)sWc;
    for (int idx = tid; idx < 1024; idx += NT) {
      int r = idx >> 7, c = idx & 127;
      W4[r*129 + c] = tf32r4(Wc4[(size_t)(d0 + r)*128 + c]);
    }
  }
  for (int l = tid; l < Lz; l += NT) sMask[l] = (unsigned char)(mask[bown*Lz + l] != 0);

  float br[4], bw[4];
#pragma unroll
  for (int g = 0; g < 4; g++) {
    br[g] = bih_r[g*256 + d] + bhh_r[g*256 + d];
    bw[g] = bih_w[g*256 + d] + bhh_w[g*256 + d];
  }
  const float bcj = bc[d0 + d_i];
  float cr_reg = (gh == 0) ? cr0[b*Dz + d] : 0.f;
  float cw_reg = (gh == 0) ? cw0[b*Dz + d] : 0.f;
  __syncthreads();

  // wcsum[j] = sum_{k=256..511} Wc[j,k] from staged (tf32) sWc; bb==0 writes.
  if (bb == 0 && tid < 64) {
    int r = tid >> 3, seg = tid & 7;
    const float* row = sWc + r*SAS + 256 + seg*32;
    float s = 0.f;
#pragma unroll
    for (int i = 0; i < 32; i++) s += row[i];
    s += __shfl_xor_sync(0xffffffffu, s, 1);
    s += __shfl_xor_sync(0xffffffffu, s, 2);
    s += __shfl_xor_sync(0xffffffffu, s, 4);
    if (seg == 0) g_wcsum[d0 + r] = s;
  }

  // ================= prologue: A(0) -> hr_0 (buffer 0) =================
  epoch_read_lstm(sA, sWr, emb, hr0, 1, g_hr, g_hrt,
                  tid, gh, b0, b, d, br, cr_reg);
  grid_bar(++bgen);

  // ================= t0: full attention over M =================
  {
    if (tid < 256) sHr[tid] = g_hr[bown*Dz + tid];
    __syncthreads();
    const int w = tid >> 5, lane = tid & 31;
    const float4* H4 = (const float4*)sHr;
    float4 h1 = H4[lane], h2 = H4[lane + 32];
    for (int l = w; l < Lz; l += 16) {
      const float4* Mr4 = (const float4*)(M + ((size_t)bown*Lz + l)*Dz);
      float4 m1 = Mr4[lane], m2 = Mr4[lane + 32];
      float s = m1.x*h1.x + m1.y*h1.y + m1.z*h1.z + m1.w*h1.w
              + m2.x*h2.x + m2.y*h2.y + m2.z*h2.z + m2.w*h2.w;
      s = warp_sum(s);
      if (lane == 0) sZ[l] = s;
    }
    __syncthreads();
    float raw[2]; float lmax = -INFINITY;
#pragma unroll
    for (int u = 0; u < 2; u++) {
      int l = tid + (u << 9);
      raw[u] = sMask[l] ? -INFINITY : sZ[l];
      lmax = fmaxf(lmax, raw[u]);
    }
    float gmax = block_max(lmax, sRed);
    float e[2]; float lsum = 0.f;
#pragma unroll
    for (int u = 0; u < 2; u++) { e[u] = __expf(raw[u] - gmax); lsum += e[u]; }
    float gsum = block_sum(lsum, sRed);
    float inv = __fdividef(1.f, gsum);
    __syncthreads();
#pragma unroll
    for (int u = 0; u < 2; u++) sZ[tid + (u << 9)] = e[u]*inv;
    __syncthreads();
    const int q = tid >> 6, dq = tid & 63;
    const float4* M4 = (const float4*)M;
    float4 acc = make_float4(0.f,0.f,0.f,0.f);
    const int lb = q << 7;
#pragma unroll 4
    for (int l = lb; l < lb + 128; l++) {
      float zv = sZ[l];
      float4 Mv = M4[((size_t)bown*Lz + l)*64 + dq];
      acc.x = fmaf(zv, Mv.x, acc.x);
      acc.y = fmaf(zv, Mv.y, acc.y);
      acc.z = fmaf(zv, Mv.z, acc.z);
      acc.w = fmaf(zv, Mv.w, acc.w);
    }
    ((float4*)sA)[q*64 + dq] = acc;
    __syncthreads();
    if (tid < 256) {
      float s = 0.f;
#pragma unroll
      for (int q2 = 0; q2 < 8; q2++) s += sA[q2*256 + tid];
      g_m[bown*Dz + tid] = s;
    }
  }
  grid_bar(++bgen);

  // ================= t0 comp gemm: [hr|m] @ Wc^T -> g_L1 =================
  {
    const float4* Hc = (const float4*)g_hrt;      // tf32 copy of hr_0
    const float4* Mm = (const float4*)g_m;
    float4* A4 = (float4*)sA;
    for (int idx = tid; idx < 4096; idx += NT) {
      int r = idx >> 7, c = idx & 127;
      if (c < 64) A4[r*129 + c] = Hc[(size_t)(b0+r)*64 + c];
      else        A4[r*129 + c] = tf32r4(Mm[(size_t)(b0+r)*64 + (c-64)]);
    }
    __syncthreads();
    {
      const int lane = tid & 31, w = tid >> 5;
      const int mt = w & 1, kh = w >> 1;
      const int gid = lane >> 2, tig = lane & 3;
      const int m0 = mt << 4;
      const int kb = kh << 6;
      const float* A0 = sA + (m0 + gid)*SAS + kb + tig;
      const float* A1 = A0 + 8*SAS;
      const float* B0 = sWc + gid*SAS + kb + tig;
      float c0=0.f,c1=0.f,c2=0.f,c3=0.f;
#pragma unroll
      for (int i = 0; i < 8; i++) {
        const int k = i << 3;
        unsigned a0 = __float_as_uint(A0[k]);
        unsigned a1 = __float_as_uint(A1[k]);
        unsigned a2 = __float_as_uint(A0[k+4]);
        unsigned a3 = __float_as_uint(A1[k+4]);
        unsigned b0r = __float_as_uint(B0[k]);
        unsigned b1r = __float_as_uint(B0[k+4]);
        MMA_TF32(c0,c1,c2,c3, a0,a1,a2,a3, b0r,b1r);
      }
      __syncthreads();
      float* r0p = sA + ((kh<<5) + m0 + gid)*9 + (tig<<1);
      float* r1p = r0p + 8*9;
      r0p[0] = c0; r0p[1] = c1;
      r1p[0] = c2; r1p[1] = c3;
    }
    __syncthreads();
    if (gh == 0) {
      float p = 0.f;
#pragma unroll
      for (int q = 0; q < 8; q++) p += sA[((q<<5) + b_i)*9 + d_i];
      g_L1[b*Dz + d0 + d_i] = p + bcj;
    }
  }
  grid_bar(++bgen);

  // ================= t0 write LSTM -> hw_0, out[0]; then A'(1) ============
  {
    const float4* Lg = (const float4*)g_L1;
    const float4* Hw = (const float4*)hw0;
    float4* A4 = (float4*)sA;
    for (int idx = tid; idx < 4096; idx += NT) {
      int r = idx >> 7, c = idx & 127;
      if (c < 64) A4[r*129 + c] = Lg[(size_t)(b0+r)*64 + c];
      else        A4[r*129 + c] = tf32r4(Hw[(size_t)(b0+r)*64 + (c-64)]);
    }
    __syncthreads();
    {
      const int lane = tid & 31, w = tid >> 5;
      const int row = (w << 1) + (lane >> 4);
      const int sub = lane & 15;
      float* Arow = sA + row*SAS;
      float mx = -INFINITY;
      for (int k = sub; k < 256; k += 16) mx = fmaxf(mx, Arow[k]);
      mx = fmaxf(mx, __shfl_xor_sync(0xffffffffu, mx, 8));
      mx = fmaxf(mx, __shfl_xor_sync(0xffffffffu, mx, 4));
      mx = fmaxf(mx, __shfl_xor_sync(0xffffffffu, mx, 2));
      mx = fmaxf(mx, __shfl_xor_sync(0xffffffffu, mx, 1));
      float sv = 0.f;
      for (int k = sub; k < 256; k += 16) { float e = __expf(Arow[k]-mx); Arow[k] = e; sv += e; }
      sv += __shfl_xor_sync(0xffffffffu, sv, 8);
      sv += __shfl_xor_sync(0xffffffffu, sv, 4);
      sv += __shfl_xor_sync(0xffffffffu, sv, 2);
      sv += __shfl_xor_sync(0xffffffffu, sv, 1);
      float inv = __fdividef(1.f, sv);
      for (int k = sub; k < 256; k += 16) Arow[k] = tf32r(Arow[k] * inv);
    }
    __syncthreads();
    float pre[4];
    gemm_lstm(sA, sWw, sA, tid, pre);
    if (gh == 0) {
      float ig = sigmf(pre[0] + bw[0]);
      float fg = sigmf(pre[1] + bw[1]);
      float gg = tanhff(pre[2] + bw[2]);
      float og = sigmf(pre[3] + bw[3]);
      cw_reg = fmaf(fg, cw_reg, ig*gg);
      float hv = og * tanhff(cw_reg);
      g_hw[b*Dz + d] = hv;                 // hw_0, buffer 0
      g_hwt[b*Dz + d] = tf32r(hv);
      out[b*Dz + d] = hv;                  // out[0]
    }
    // A'(1): hr_1 = LSTMr(emb[1], hr_0) -> buffer 1 (pre-rounded inputs)
    epoch_read_lstm(sA, sWr, g_embt + BD, g_hrt, 0, g_hr + BD, g_hrt + BD,
                    tid, gh, b0, b, d, br, cr_reg);
  }
  grid_bar(++bgen);

  // ================= steps t = 1 .. 31 =================
  for (int t = 1; t < Tz; t++) {
    const int cur = t & 1, prev = cur ^ 1;
    float* hrc = g_hr + cur*BD;
    const float* hwp = g_hw + prev*BD;
    float* hwc = g_hw + cur*BD;

    // ============ epoch B: attention + L1/L2 gemms ============
    {
      {
        const float4* Hc = (const float4*)(g_hrt + cur*BD);
        const float4* Hw = (const float4*)(g_hwt + prev*BD);
        float4* A4 = (float4*)sA;
        for (int idx = tid; idx < 4096; idx += NT) {
          int r = idx >> 7, c = idx & 127;
          float4 v = (c < 64) ? Hc[(size_t)(b0+r)*64 + c] : Hw[(size_t)(b0+r)*64 + (c-64)];
          A4[r*129 + c] = v;
        }
      }
      if (tid < 256) { sHr[tid] = hrc[bown*Dz + tid]; sHw[tid] = hwp[bown*Dz + tid]; }
      __syncthreads();
      float hrv = (tid < 256) ? sHr[tid] : 0.f;
      float hwv = (tid < 256) ? sHw[tid] : 0.f;
      float Shr, dot;
      block_sum2(hrv, hrv*hwv, sRed, Shr, dot);
      float alpha = dot - Shr;
      float zp[2], raw[2]; float lmax = -INFINITY;
#pragma unroll
      for (int u = 0; u < 2; u++) {
        int l = tid + (u << 9);
        zp[u] = sZ[l];
        raw[u] = sMask[l] ? -INFINITY : fmaf(zp[u], alpha, Shr);
        lmax = fmaxf(lmax, raw[u]);
      }
      float gmax = block_max(lmax, sRed);
      float e[2]; float lsum = 0.f, lt = 0.f;
#pragma unroll
      for (int u = 0; u < 2; u++) { e[u] = __expf(raw[u] - gmax); lsum += e[u]; lt += e[u]*zp[u]; }
      float gsum, gt;
      block_sum2(lsum, lt, sRed, gsum, gt);
      float inv = __fdividef(1.f, gsum);
      __syncthreads();
#pragma unroll
      for (int u = 0; u < 2; u++) sZ[tid + (u << 9)] = e[u]*inv;
      float S = gt * inv;
      if (tid == 0) g_S[bown] = S;
      __syncthreads();

      // L1/L2 gemms: 16 warps = g(2) x mt(2) x kh(4 of k64). C = 32b x 8j each.
      {
        const int lane = tid & 31, w = tid >> 5;
        const int g = w >> 3, w7 = w & 7;
        const int mt = w7 & 1, kh = w7 >> 1;
        const int gid = lane >> 2, tig = lane & 3;
        const int m0 = mt << 4;
        const int kb = (g << 8) + (kh << 6);
        const float* A0 = sA + (m0 + gid)*SAS + kb + tig;
        const float* A1 = A0 + 8*SAS;
        const float* B0 = sWc + gid*SAS + kb + tig;
        float c0=0.f,c1=0.f,c2=0.f,c3=0.f;
#pragma unroll
        for (int i = 0; i < 8; i++) {
          const int k = i << 3;
          unsigned a0 = __float_as_uint(A0[k]);
          unsigned a1 = __float_as_uint(A1[k]);
          unsigned a2 = __float_as_uint(A0[k+4]);
          unsigned a3 = __float_as_uint(A1[k+4]);
          unsigned b0r = __float_as_uint(B0[k]);
          unsigned b1r = __float_as_uint(B0[k+4]);
          MMA_TF32(c0,c1,c2,c3, a0,a1,a2,a3, b0r,b1r);
        }
        __syncthreads();   // all sA reads complete before partial overwrite
        float* r0p = sA + ((g*4 + kh)*288) + (m0 + gid)*9 + (tig<<1);
        float* r1p = r0p + 8*9;
        r0p[0] = c0; r0p[1] = c1;
        r1p[0] = c2; r1p[1] = c3;
      }
      __syncthreads();
      if (gh == 0) {
        float l1 = 0.f, l2 = 0.f;
#pragma unroll
        for (int q = 0; q < 4; q++) {
          l1 += sA[q*288     + b_i*9 + d_i];
          l2 += sA[(4+q)*288 + b_i*9 + d_i];
        }
        g_L1[b*Dz + d0 + d_i] = l1;
        g_L2[b*Dz + d0 + d_i] = l2;
      }
    }
    bar_arrive(++bgen);

    // ============ A'(t+1) between arrive and wait ============
    if (t < Tz - 1) {
      // hr_{t+1} -> buffer prev. Inputs pre-rounded (g_embt, g_hrt cur).
      epoch_read_lstm(sA, sWr, g_embt + (size_t)(t+1)*BD, g_hrt + cur*BD, 0,
                      g_hr + prev*BD, g_hrt + prev*BD,
                      tid, gh, b0, b, d, br, cr_reg);
    }
    bar_wait(bgen);

    // ============ epoch C: assemble logits + softmax + write LSTM ============
    {
      const float4* L14 = (const float4*)g_L1;
      const float4* L24 = (const float4*)g_L2;
      const float4* WS4 = (const float4*)g_wcsum;
      const float4* BC4 = (const float4*)bc;
      const float4* Hw  = (const float4*)(g_hwt + prev*BD);
      float4* A4 = (float4*)sA;
      for (int idx = tid; idx < 4096; idx += NT) {
        int r = idx >> 7, c = idx & 127;
        if (c < 64) {
          float Sb = g_S[b0 + r];
          float4 l1 = L14[(size_t)(b0+r)*64 + c];
          float4 l2 = L24[(size_t)(b0+r)*64 + c];
          float4 wsv = WS4[c];
          float4 bcv = BC4[c];
          float4 o;
          o.x = l1.x + Sb*l2.x + (1.f-Sb)*wsv.x + bcv.x;
          o.y = l1.y + Sb*l2.y + (1.f-Sb)*wsv.y + bcv.y;
          o.z = l1.z + Sb*l2.z + (1.f-Sb)*wsv.z + bcv.z;
          o.w = l1.w + Sb*l2.w + (1.f-Sb)*wsv.w + bcv.w;
          A4[r*129 + c] = o;
        } else {
          A4[r*129 + c] = Hw[(size_t)(b0+r)*64 + (c-64)];
        }
      }
      __syncthreads();
      {
        const int lane = tid & 31, w = tid >> 5;
        const int row = (w << 1) + (lane >> 4);
        const int sub = lane & 15;
        float* Arow = sA + row*SAS;
        float mx = -INFINITY;
        for (int k = sub; k < 256; k += 16) mx = fmaxf(mx, Arow[k]);
        mx = fmaxf(mx, __shfl_xor_sync(0xffffffffu, mx, 8));
        mx = fmaxf(mx, __shfl_xor_sync(0xffffffffu, mx, 4));
        mx = fmaxf(mx, __shfl_xor_sync(0xffffffffu, mx, 2));
        mx = fmaxf(mx, __shfl_xor_sync(0xffffffffu, mx, 1));
        float sv = 0.f;
        for (int k = sub; k < 256; k += 16) { float e = __expf(Arow[k]-mx); Arow[k] = e; sv += e; }
        sv += __shfl_xor_sync(0xffffffffu, sv, 8);
        sv += __shfl_xor_sync(0xffffffffu, sv, 4);
        sv += __shfl_xor_sync(0xffffffffu, sv, 2);
        sv += __shfl_xor_sync(0xffffffffu, sv, 1);
        float inv = __fdividef(1.f, sv);
        for (int k = sub; k < 256; k += 16) Arow[k] = tf32r(Arow[k] * inv);
      }
      __syncthreads();
      float pre[4];
      gemm_lstm(sA, sWw, sA, tid, pre);
      if (gh == 0) {
        float ig = sigmf(pre[0] + bw[0]);
        float fg = sigmf(pre[1] + bw[1]);
        float gg = tanhff(pre[2] + bw[2]);
        float og = sigmf(pre[3] + bw[3]);
        cw_reg = fmaf(fg, cw_reg, ig*gg);
        float hv = og * tanhff(cw_reg);
        hwc[b*Dz + d] = hv;
        g_hwt[cur*BD + b*Dz + d] = tf32r(hv);
        out[(size_t)t*BD + b*Dz + d] = hv;
      }
    }
    grid_bar(++bgen);   // covers hr_{t+1} (A') and hw_t (C) for B(t+1)/epilogue
  }

  // ================= final: states + M materialization =================
  if (tid < 256) {
    int i = cta*256 + tid;
    out[1048576 + i]         = g_hr[BD + i];   // hr_31 (buffer 1)
    out[1048576 + 65536 + i] = g_hw[BD + i];   // hw_31 (buffer 1)
  }
  if (gh == 0) {
    out[1048576 + 32768 + b*Dz + d] = cr_reg;
    out[1048576 + 98304 + b*Dz + d] = cw_reg;
  }
  {
    if (tid < 256) sHw[tid] = g_hw[BD + bown*Dz + tid];
    __syncthreads();
    const int dq = tid & 63;
    const int lr = tid >> 6;
    float4 hv4 = ((const float4*)sHw)[dq];
    float4 h1;
    h1.x = hv4.x - 1.f; h1.y = hv4.y - 1.f; h1.z = hv4.z - 1.f; h1.w = hv4.w - 1.f;
    float* Mo = out + 1179648 + (size_t)bown*Lz*Dz;
    for (int l = lr; l < Lz; l += 8) {
      float zv = sZ[l];
      float4 o;
      o.x = fmaf(h1.x, zv, 1.f);
      o.y = fmaf(h1.y, zv, 1.f);
      o.z = fmaf(h1.z, zv, 1.f);
      o.w = fmaf(h1.w, zv, 1.f);
      ((float4*)(Mo + (size_t)l*Dz))[dq] = o;
    }
  }
}

// ---------------- zero the barrier flags before each graph replay ----------
__global__ void zero_flags(){
  g_flags[threadIdx.x*32 + blockIdx.x] = 0u;
}

// ---------------- launch ----------------
extern "C" void kernel_launch(void* const* d_in, const int* in_sizes, int n_in,
                              void* d_out, int out_size)
{
  const float* emb   = (const float*)d_in[0];
  const float* hr0   = (const float*)d_in[1];
  const float* cr0   = (const float*)d_in[2];
  const float* hw0   = (const float*)d_in[3];
  const float* cw0   = (const float*)d_in[4];
  const float* M     = (const float*)d_in[5];
  const int*   mask  = (const int*)d_in[6];
  const float* Wih_r = (const float*)d_in[7];
  const float* Whh_r = (const float*)d_in[8];
  const float* bih_r = (const float*)d_in[9];
  const float* bhh_r = (const float*)d_in[10];
  const float* Wc    = (const float*)d_in[11];
  const float* bc    = (const float*)d_in[12];
  const float* Wih_w = (const float*)d_in[13];
  const float* Whh_w = (const float*)d_in[14];
  const float* bih_w = (const float*)d_in[15];
  const float* bhh_w = (const float*)d_in[16];
  float* out = (float*)d_out;

  zero_flags<<<32, NCTA>>>();

  cudaFuncSetAttribute(mega, cudaFuncAttributeMaxDynamicSharedMemorySize, SMEM_BYTES);
  mega<<<NCTA, NT, SMEM_BYTES>>>(emb, hr0, cr0, hw0, cw0, M, mask,
                                 Wih_r, Whh_r, bih_r, bhh_r, Wc, bc,
                                 Wih_w, Whh_w, bih_w, bhh_w, out);
}

// round 17
// speedup vs baseline: 1.1898x; 1.1898x over previous
#include <cuda_runtime.h>
#include <cuda_fp16.h>
#include <math.h>

#define NCTA 128
#define NT 512
#define Bz 128
#define Lz 1024
#define Dz 256
#define Tz 32
#define BD (Bz*Dz)      /* 32768 */
#define STRH 520        /* smem row stride in halves (conflict-free) */

// smem byte offsets
#define OFFB_WR   0        /* 32x520 halves = 33280 B */
#define OFFB_WW   33280
#define OFFB_WC   66560    /* 8x520 halves = 8320 B */
#define OFFB_A    74880    /* 32x520 halves = 33280 B; aliased by fp32 sP */
#define OFFB_Z    108160   /* 1024 floats */
#define OFFB_HR   112256   /* 256 floats */
#define OFFB_HW   113280   /* 256 floats */
#define OFFB_RED  114304   /* 32 floats */
#define OFFB_MASK 114432   /* 1024 B */
#define SMEM_BYTES 115456

// ---------------- scratch ----------------
__device__ __align__(16) float  g_hr[2*BD];
__device__ __align__(16) float  g_hw[2*BD];
__device__ __align__(16) __half g_hrt[2*BD];    // fp16 copies of hr
__device__ __align__(16) __half g_hwt[2*BD];    // fp16 copies of hw
__device__ __align__(16) __half g_embt[Tz*BD];  // fp16 emb (t>=1 used)
__device__ __align__(16) float  g_m[BD];
__device__ __align__(16) float  g_L1[BD];
__device__ __align__(16) float  g_L2[BD];
__device__ __align__(16) float  g_S[Bz];
__device__ __align__(16) float  g_wcsum[Dz];
__device__ unsigned g_flags[NCTA*32];

// ---------------- helpers ----------------
__device__ __forceinline__ float warp_sum(float v){
#pragma unroll
  for (int o=16;o;o>>=1) v += __shfl_xor_sync(0xffffffffu,v,o);
  return v;
}
__device__ __forceinline__ float block_sum(float v, float* sbuf){
  v = warp_sum(v);
  int lane = threadIdx.x & 31, w = threadIdx.x >> 5;
  __syncthreads();
  if (lane == 0) sbuf[w] = v;
  __syncthreads();
  float r = sbuf[0];
#pragma unroll
  for (int i=1;i<16;i++) r += sbuf[i];
  return r;
}
__device__ __forceinline__ void block_sum2(float a, float b, float* sbuf,
                                           float& ra, float& rb){
  a = warp_sum(a); b = warp_sum(b);
  int lane = threadIdx.x & 31, w = threadIdx.x >> 5;
  __syncthreads();
  if (lane == 0) { sbuf[w] = a; sbuf[16 + w] = b; }
  __syncthreads();
  float xa = sbuf[0], xb = sbuf[16];
#pragma unroll
  for (int i=1;i<16;i++) { xa += sbuf[i]; xb += sbuf[16 + i]; }
  ra = xa; rb = xb;
}
__device__ __forceinline__ float block_max(float v, float* sbuf){
#pragma unroll
  for (int o=16;o;o>>=1) v = fmaxf(v, __shfl_xor_sync(0xffffffffu,v,o));
  int lane = threadIdx.x & 31, w = threadIdx.x >> 5;
  __syncthreads();
  if (lane == 0) sbuf[w] = v;
  __syncthreads();
  float r = sbuf[0];
#pragma unroll
  for (int i=1;i<16;i++) r = fmaxf(r, sbuf[i]);
  return r;
}
__device__ __forceinline__ float sigmf(float x){
  return __fdividef(1.f, 1.f + __expf(-x));
}
__device__ __forceinline__ float tanhff(float x){
  float e = __expf(2.f*x);
  return 1.f - __fdividef(2.f, e + 1.f);
}
__device__ __forceinline__ uint2 f4_to_h4(float4 v){
  __half2 lo = __floats2half2_rn(v.x, v.y);
  __half2 hi = __floats2half2_rn(v.z, v.w);
  uint2 u;
  u.x = *(unsigned*)&lo;
  u.y = *(unsigned*)&hi;
  return u;
}

// grid barrier split: arrive / wait (R7 flag pattern)
__device__ __forceinline__ void bar_arrive(unsigned gen){
  __syncthreads();
  if (threadIdx.x == 0) {
    __threadfence();
    *(volatile unsigned*)&g_flags[blockIdx.x*32] = gen;
  }
}
__device__ __forceinline__ void bar_wait(unsigned gen){
  if (threadIdx.x < NCTA) {
    while (*(volatile unsigned*)&g_flags[threadIdx.x*32] < gen) { }
  }
  __syncthreads();
  if (threadIdx.x == 0) __threadfence();
  __syncthreads();
}
__device__ __forceinline__ void grid_bar(unsigned gen){
  bar_arrive(gen);
  bar_wait(gen);
}

#define MMA_F16(c0,c1,c2,c3,a0,a1,a2,a3,b0,b1) \
  asm volatile("mma.sync.aligned.m16n8k16.row.col.f32.f16.f16.f32 " \
    "{%0,%1,%2,%3}, {%4,%5,%6,%7}, {%8,%9}, {%0,%1,%2,%3};" \
    : "+f"(c0),"+f"(c1),"+f"(c2),"+f"(c3) \
    : "r"(a0),"r"(a1),"r"(a2),"r"(a3),"r"(b0),"r"(b1))

#define LDU(p) (*(const unsigned*)(p))

// LSTM GEMM fp16: C[32b x 32j] = A[32x512]*W^T. 16 warps = mt(2) x ntt(2) x
// kh(4 of k128). 8 iters of k16. sP (fp32) aliases sAh. pre[4] for tid<256.
// Trailing __syncthreads so callers may restage sAh right after.
__device__ __forceinline__ void gemm_lstm_h(
    const __half* sAh, const __half* sWh, float* sP, int tid, float* pre)
{
  const int lane = tid & 31, w = tid >> 5;
  const int kh = w & 3, mt = (w >> 2) & 1, ntt = w >> 3;
  const int gid = lane >> 2, tig = lane & 3;
  const int m0 = mt << 4, n0 = ntt << 4;
  const int kb = kh << 7;
  const __half* A0 = sAh + (m0 + gid)*STRH + kb + tig*2;
  const __half* A1 = A0 + 8*STRH;
  const __half* B0 = sWh + (n0 + gid)*STRH + kb + tig*2;
  const __half* B1 = B0 + 8*STRH;

  float c00=0.f,c01=0.f,c02=0.f,c03=0.f;
  float c10=0.f,c11=0.f,c12=0.f,c13=0.f;
#pragma unroll
  for (int i = 0; i < 8; i++) {
    const int k = i << 4;
    unsigned a0 = LDU(A0 + k);
    unsigned a1 = LDU(A1 + k);
    unsigned a2 = LDU(A0 + k + 8);
    unsigned a3 = LDU(A1 + k + 8);
    unsigned b0 = LDU(B0 + k);
    unsigned b1 = LDU(B0 + k + 8);
    unsigned b2 = LDU(B1 + k);
    unsigned b3 = LDU(B1 + k + 8);
    MMA_F16(c00,c01,c02,c03, a0,a1,a2,a3, b0,b1);
    MMA_F16(c10,c11,c12,c13, a0,a1,a2,a3, b2,b3);
  }
  __syncthreads();               // all sAh reads complete before overwrite
  {
    float* r0p = sP + ((kh<<5) + m0 + gid)*33 + n0 + (tig<<1);
    float* r1p = r0p + 8*33;
    r0p[0] = c00; r0p[1] = c01;
    r1p[0] = c02; r1p[1] = c03;
    r0p[8] = c10; r0p[9] = c11;
    r1p[8] = c12; r1p[9] = c13;
  }
  __syncthreads();
  if (tid < 256) {
    const int b_i = tid >> 3, d_i = tid & 7;
#pragma unroll
    for (int g = 0; g < 4; g++) {
      float s = 0.f;
#pragma unroll
      for (int q = 0; q < 4; q++) s += sP[((q<<5) + b_i)*33 + g*8 + d_i];
      pre[g] = s;
    }
  }
  __syncthreads();               // combine reads done before caller writes sAh
}

// read-LSTM epoch: stage [x|h] (conv: fp32 sources; else fp16 copies),
// gemm vs sWrh, pointwise -> hr fp32 + fp16 copy.
// FP16 source rows are 256 halves = 32 uint4 (uint4 = 8 halves).
__device__ __forceinline__ void epoch_read_lstm(
    __half* sAh, const __half* sWrh, float* sP,
    const void* xp, const void* hp, int conv,
    float* __restrict__ hr_out, __half* __restrict__ hrt_out,
    int tid, int gh, int b0, int b, int d,
    const float* br, float& cr_reg)
{
  if (conv) {
    const float4* X = (const float4*)xp;
    const float4* H = (const float4*)hp;
    for (int idx = tid; idx < 4096; idx += NT) {
      int r = idx >> 7, c = idx & 127;
      float4 v = (c < 64) ? X[(size_t)(b0+r)*64 + c] : H[(size_t)(b0+r)*64 + (c-64)];
      *(uint2*)(sAh + r*STRH + c*4) = f4_to_h4(v);
    }
  } else {
    const uint4* X = (const uint4*)xp;
    const uint4* H = (const uint4*)hp;
    for (int idx = tid; idx < 2048; idx += NT) {
      int r = idx >> 6, c = idx & 63;
      uint4 v = (c < 32) ? X[(size_t)(b0+r)*32 + c] : H[(size_t)(b0+r)*32 + (c-32)];
      *(uint4*)(sAh + r*STRH + c*8) = v;
    }
  }
  __syncthreads();
  float pre[4];
  gemm_lstm_h(sAh, sWrh, sP, tid, pre);
  if (gh == 0) {
    float ig = sigmf(pre[0] + br[0]);
    float fg = sigmf(pre[1] + br[1]);
    float gg = tanhff(pre[2] + br[2]);
    float og = sigmf(pre[3] + br[3]);
    cr_reg = fmaf(fg, cr_reg, ig*gg);
    float hv = og * tanhff(cr_reg);
    hr_out[b*Dz + d] = hv;
    hrt_out[b*Dz + d] = __float2half(hv);
  }
}

// ---------------- the persistent mega-kernel ----------------
__global__ __launch_bounds__(NT,1) void mega(
  const float* __restrict__ emb, const float* __restrict__ hr0,
  const float* __restrict__ cr0, const float* __restrict__ hw0,
  const float* __restrict__ cw0, const float* __restrict__ M,
  const int* __restrict__ mask,
  const float* __restrict__ Wih_r, const float* __restrict__ Whh_r,
  const float* __restrict__ bih_r, const float* __restrict__ bhh_r,
  const float* __restrict__ Wc,    const float* __restrict__ bc,
  const float* __restrict__ Wih_w, const float* __restrict__ Whh_w,
  const float* __restrict__ bih_w, const float* __restrict__ bhh_w,
  float* __restrict__ out)
{
  extern __shared__ __align__(16) unsigned char smraw[];
  __half* sWrh = (__half*)(smraw + OFFB_WR);
  __half* sWwh = (__half*)(smraw + OFFB_WW);
  __half* sWch = (__half*)(smraw + OFFB_WC);
  __half* sAh  = (__half*)(smraw + OFFB_A);
  float*  sP   = (float*)(smraw + OFFB_A);     // alias
  float*  sZ   = (float*)(smraw + OFFB_Z);
  float*  sHr  = (float*)(smraw + OFFB_HR);
  float*  sHw  = (float*)(smraw + OFFB_HW);
  float*  sRed = (float*)(smraw + OFFB_RED);
  unsigned char* sMask = smraw + OFFB_MASK;

  const int tid = threadIdx.x;
  const int cta = blockIdx.x;
  const int jb = cta >> 2;
  const int bb = cta & 3;
  const int b0 = bb << 5;
  const int d0 = jb << 3;
  const int cell = tid & 255;
  const int b_i = cell >> 3, d_i = cell & 7;
  const int gh = tid >> 8;
  const int b = b0 + b_i, d = d0 + d_i;
  const int bown = cta;
  unsigned bgen = 0;

  // ---- emb preconversion for t>=1 (ordered before A'(1) by grid bars) ----
  {
    const float4* E4 = (const float4*)(emb + BD);
    uint2* ET = (uint2*)(g_embt + BD);
    const int per = ((Tz-1)*BD/4) / NCTA;   // 1984
    const int base = cta * per;
    for (int i = tid; i < per; i += NT) ET[base + i] = f4_to_h4(E4[base + i]);
  }

  // ---- one-time weight staging (fp16) ----
  {
    const float4* Wi = (const float4*)Wih_r;
    const float4* Wh = (const float4*)Whh_r;
    for (int idx = tid; idx < 4096; idx += NT) {
      int r = idx >> 7, c = idx & 127;
      int j = ((r >> 3) << 8) + d0 + (r & 7);
      float4 v = (c < 64) ? Wi[(size_t)j*64 + c] : Wh[(size_t)j*64 + (c-64)];
      *(uint2*)(sWrh + r*STRH + c*4) = f4_to_h4(v);
    }
  }
  {
    const float4* Wi = (const float4*)Wih_w;
    const float4* Wh = (const float4*)Whh_w;
    for (int idx = tid; idx < 4096; idx += NT) {
      int r = idx >> 7, c = idx & 127;
      int j = ((r >> 3) << 8) + d0 + (r & 7);
      float4 v = (c < 64) ? Wi[(size_t)j*64 + c] : Wh[(size_t)j*64 + (c-64)];
      *(uint2*)(sWwh + r*STRH + c*4) = f4_to_h4(v);
    }
  }
  {
    const float4* Wc4 = (const float4*)Wc;
    for (int idx = tid; idx < 1024; idx += NT) {
      int r = idx >> 7, c = idx & 127;
      *(uint2*)(sWch + r*STRH + c*4) = f4_to_h4(Wc4[(size_t)(d0 + r)*128 + c]);
    }
  }
  for (int l = tid; l < Lz; l += NT) sMask[l] = (unsigned char)(mask[bown*Lz + l] != 0);

  float br[4], bw[4];
#pragma unroll
  for (int g = 0; g < 4; g++) {
    br[g] = bih_r[g*256 + d] + bhh_r[g*256 + d];
    bw[g] = bih_w[g*256 + d] + bhh_w[g*256 + d];
  }
  float cr_reg = (gh == 0) ? cr0[b*Dz + d] : 0.f;
  float cw_reg = (gh == 0) ? cw0[b*Dz + d] : 0.f;
  __syncthreads();

  // wcsum[j] = sum_{k=256..511} Wc[j,k] from staged fp16 sWch; bb==0 writes.
  if (bb == 0 && tid < 64) {
    int r = tid >> 3, seg = tid & 7;
    const __half* row = sWch + r*STRH + 256 + seg*32;
    float s = 0.f;
#pragma unroll
    for (int i = 0; i < 32; i++) s += __half2float(row[i]);
    s += __shfl_xor_sync(0xffffffffu, s, 1);
    s += __shfl_xor_sync(0xffffffffu, s, 2);
    s += __shfl_xor_sync(0xffffffffu, s, 4);
    if (seg == 0) g_wcsum[d0 + r] = s;
  }

  // ================= prologue: A(0) -> hr_0 (buffer 0) =================
  epoch_read_lstm(sAh, sWrh, sP, emb, hr0, 1, g_hr, g_hrt,
                  tid, gh, b0, b, d, br, cr_reg);
  grid_bar(++bgen);

  // ================= t0: full attention over M =================
  {
    if (tid < 256) sHr[tid] = g_hr[bown*Dz + tid];
    __syncthreads();
    const int w = tid >> 5, lane = tid & 31;
    const float4* H4 = (const float4*)sHr;
    float4 h1 = H4[lane], h2 = H4[lane + 32];
    for (int l = w; l < Lz; l += 16) {
      const float4* Mr4 = (const float4*)(M + ((size_t)bown*Lz + l)*Dz);
      float4 m1 = Mr4[lane], m2 = Mr4[lane + 32];
      float s = m1.x*h1.x + m1.y*h1.y + m1.z*h1.z + m1.w*h1.w
              + m2.x*h2.x + m2.y*h2.y + m2.z*h2.z + m2.w*h2.w;
      s = warp_sum(s);
      if (lane == 0) sZ[l] = s;
    }
    __syncthreads();
    float raw[2]; float lmax = -INFINITY;
#pragma unroll
    for (int u = 0; u < 2; u++) {
      int l = tid + (u << 9);
      raw[u] = sMask[l] ? -INFINITY : sZ[l];
      lmax = fmaxf(lmax, raw[u]);
    }
    float gmax = block_max(lmax, sRed);
    float e[2]; float lsum = 0.f;
#pragma unroll
    for (int u = 0; u < 2; u++) { e[u] = __expf(raw[u] - gmax); lsum += e[u]; }
    float gsum = block_sum(lsum, sRed);
    float inv = __fdividef(1.f, gsum);
    __syncthreads();
#pragma unroll
    for (int u = 0; u < 2; u++) sZ[tid + (u << 9)] = e[u]*inv;
    __syncthreads();
    const int q = tid >> 6, dq = tid & 63;
    const float4* M4 = (const float4*)M;
    float4 acc = make_float4(0.f,0.f,0.f,0.f);
    const int lb = q << 7;
#pragma unroll 4
    for (int l = lb; l < lb + 128; l++) {
      float zv = sZ[l];
      float4 Mv = M4[((size_t)bown*Lz + l)*64 + dq];
      acc.x = fmaf(zv, Mv.x, acc.x);
      acc.y = fmaf(zv, Mv.y, acc.y);
      acc.z = fmaf(zv, Mv.z, acc.z);
      acc.w = fmaf(zv, Mv.w, acc.w);
    }
    ((float4*)sP)[q*64 + dq] = acc;
    __syncthreads();
    if (tid < 256) {
      float s = 0.f;
#pragma unroll
      for (int q2 = 0; q2 < 8; q2++) s += sP[q2*256 + tid];
      g_m[bown*Dz + tid] = s;
    }
  }
  grid_bar(++bgen);

  // ================= t0 comp gemm: [hr|m] @ Wc^T -> g_L1 =================
  {
    // stage: hrt fp16 copy (cols 0..255 = 32 uint4/row) + m fp32->fp16
    const uint4* Hc = (const uint4*)g_hrt;
    for (int idx = tid; idx < 1024; idx += NT) {
      int r = idx >> 5, c = idx & 31;
      *(uint4*)(sAh + r*STRH + c*8) = Hc[(size_t)(b0+r)*32 + c];
    }
    const float4* Mm = (const float4*)g_m;
    for (int idx = tid; idx < 2048; idx += NT) {
      int r = idx >> 6, c = idx & 63;
      *(uint2*)(sAh + r*STRH + 256 + c*4) = f4_to_h4(Mm[(size_t)(b0+r)*64 + c]);
    }
    __syncthreads();
    {
      const int lane = tid & 31, w = tid >> 5;
      const int mt = w & 1, kh = w >> 1;        // kh 0..7 of k64
      const int gid = lane >> 2, tig = lane & 3;
      const int m0 = mt << 4;
      const int kb = kh << 6;
      const __half* A0 = sAh + (m0 + gid)*STRH + kb + tig*2;
      const __half* A1 = A0 + 8*STRH;
      const __half* B0 = sWch + gid*STRH + kb + tig*2;
      float c0=0.f,c1=0.f,c2=0.f,c3=0.f;
#pragma unroll
      for (int i = 0; i < 4; i++) {
        const int k = i << 4;
        unsigned a0 = LDU(A0 + k);
        unsigned a1 = LDU(A1 + k);
        unsigned a2 = LDU(A0 + k + 8);
        unsigned a3 = LDU(A1 + k + 8);
        unsigned b0r = LDU(B0 + k);
        unsigned b1r = LDU(B0 + k + 8);
        MMA_F16(c0,c1,c2,c3, a0,a1,a2,a3, b0r,b1r);
      }
      __syncthreads();
      float* r0p = sP + ((kh<<5) + m0 + gid)*9 + (tig<<1);
      float* r1p = r0p + 8*9;
      r0p[0] = c0; r0p[1] = c1;
      r1p[0] = c2; r1p[1] = c3;
    }
    __syncthreads();
    if (gh == 0) {
      float p = 0.f;
#pragma unroll
      for (int q = 0; q < 8; q++) p += sP[((q<<5) + b_i)*9 + d_i];
      g_L1[b*Dz + d0 + d_i] = p + bc[d0 + d_i];
    }
  }
  grid_bar(++bgen);

  // ============ t0 write LSTM -> hw_0, out[0]; then A'(1) ============
  {
    // fused softmax of g_L1 rows (registers) -> sAh cols 0..255
    {
      const int lane = tid & 31, w = tid >> 5;
      const int row = (w << 1) + (lane >> 4);
      const int sub = lane & 15;
      float vals[16]; float mx = -INFINITY;
#pragma unroll
      for (int k = 0; k < 16; k++) {
        float o = g_L1[(size_t)(b0+row)*Dz + sub + (k<<4)];
        vals[k] = o; mx = fmaxf(mx, o);
      }
      mx = fmaxf(mx, __shfl_xor_sync(0xffffffffu, mx, 8));
      mx = fmaxf(mx, __shfl_xor_sync(0xffffffffu, mx, 4));
      mx = fmaxf(mx, __shfl_xor_sync(0xffffffffu, mx, 2));
      mx = fmaxf(mx, __shfl_xor_sync(0xffffffffu, mx, 1));
      float sv = 0.f;
#pragma unroll
      for (int k = 0; k < 16; k++) { vals[k] = __expf(vals[k]-mx); sv += vals[k]; }
      sv += __shfl_xor_sync(0xffffffffu, sv, 8);
      sv += __shfl_xor_sync(0xffffffffu, sv, 4);
      sv += __shfl_xor_sync(0xffffffffu, sv, 2);
      sv += __shfl_xor_sync(0xffffffffu, sv, 1);
      float inv = __fdividef(1.f, sv);
#pragma unroll
      for (int k = 0; k < 16; k++)
        sAh[row*STRH + sub + (k<<4)] = __float2half(vals[k]*inv);
    }
    // stage hw0 fp32 -> fp16 (cols 256..511)
    {
      const float4* Hw = (const float4*)hw0;
      for (int idx = tid; idx < 2048; idx += NT) {
        int r = idx >> 6, c = idx & 63;
        *(uint2*)(sAh + r*STRH + 256 + c*4) = f4_to_h4(Hw[(size_t)(b0+r)*64 + c]);
      }
    }
    __syncthreads();
    float pre[4];
    gemm_lstm_h(sAh, sWwh, sP, tid, pre);
    if (gh == 0) {
      float ig = sigmf(pre[0] + bw[0]);
      float fg = sigmf(pre[1] + bw[1]);
      float gg = tanhff(pre[2] + bw[2]);
      float og = sigmf(pre[3] + bw[3]);
      cw_reg = fmaf(fg, cw_reg, ig*gg);
      float hv = og * tanhff(cw_reg);
      g_hw[b*Dz + d] = hv;
      g_hwt[b*Dz + d] = __float2half(hv);
      out[b*Dz + d] = hv;
    }
    // A'(1): hr_1 = LSTMr(emb[1], hr_0) -> buffer 1 (fp16 inputs)
    epoch_read_lstm(sAh, sWrh, sP, g_embt + BD, g_hrt, 0, g_hr + BD, g_hrt + BD,
                    tid, gh, b0, b, d, br, cr_reg);
  }
  grid_bar(++bgen);

  // ================= steps t = 1 .. 31 =================
  for (int t = 1; t < Tz; t++) {
    const int cur = t & 1, prev = cur ^ 1;
    float* hrc = g_hr + cur*BD;
    const float* hwp = g_hw + prev*BD;
    float* hwc = g_hw + cur*BD;

    // ============ epoch B: attention + L1/L2 gemms ============
    {
      {
        const uint4* Hc = (const uint4*)(g_hrt + cur*BD);
        const uint4* Hw = (const uint4*)(g_hwt + prev*BD);
        for (int idx = tid; idx < 2048; idx += NT) {
          int r = idx >> 6, c = idx & 63;
          uint4 v = (c < 32) ? Hc[(size_t)(b0+r)*32 + c] : Hw[(size_t)(b0+r)*32 + (c-32)];
          *(uint4*)(sAh + r*STRH + c*8) = v;
        }
      }
      if (tid < 256) { sHr[tid] = hrc[bown*Dz + tid]; sHw[tid] = hwp[bown*Dz + tid]; }
      __syncthreads();
      float hrv = (tid < 256) ? sHr[tid] : 0.f;
      float hwv = (tid < 256) ? sHw[tid] : 0.f;
      float Shr, dot;
      block_sum2(hrv, hrv*hwv, sRed, Shr, dot);
      float alpha = dot - Shr;
      float zp[2], raw[2]; float lmax = -INFINITY;
#pragma unroll
      for (int u = 0; u < 2; u++) {
        int l = tid + (u << 9);
        zp[u] = sZ[l];
        raw[u] = sMask[l] ? -INFINITY : fmaf(zp[u], alpha, Shr);
        lmax = fmaxf(lmax, raw[u]);
      }
      float gmax = block_max(lmax, sRed);
      float e[2]; float lsum = 0.f, lt = 0.f;
#pragma unroll
      for (int u = 0; u < 2; u++) { e[u] = __expf(raw[u] - gmax); lsum += e[u]; lt += e[u]*zp[u]; }
      float gsum, gt;
      block_sum2(lsum, lt, sRed, gsum, gt);
      float inv = __fdividef(1.f, gsum);
      __syncthreads();
#pragma unroll
      for (int u = 0; u < 2; u++) sZ[tid + (u << 9)] = e[u]*inv;
      float S = gt * inv;
      if (tid == 0) g_S[bown] = S;
      __syncthreads();

      // L1/L2 gemms: 16 warps = g(2) x mt(2) x kh(4 of k64)
      {
        const int lane = tid & 31, w = tid >> 5;
        const int g = w >> 3, w7 = w & 7;
        const int mt = w7 & 1, kh = w7 >> 1;
        const int gid = lane >> 2, tig = lane & 3;
        const int m0 = mt << 4;
        const int kb = (g << 8) + (kh << 6);
        const __half* A0 = sAh + (m0 + gid)*STRH + kb + tig*2;
        const __half* A1 = A0 + 8*STRH;
        const __half* B0 = sWch + gid*STRH + kb + tig*2;
        float c0=0.f,c1=0.f,c2=0.f,c3=0.f;
#pragma unroll
        for (int i = 0; i < 4; i++) {
          const int k = i << 4;
          unsigned a0 = LDU(A0 + k);
          unsigned a1 = LDU(A1 + k);
          unsigned a2 = LDU(A0 + k + 8);
          unsigned a3 = LDU(A1 + k + 8);
          unsigned b0r = LDU(B0 + k);
          unsigned b1r = LDU(B0 + k + 8);
          MMA_F16(c0,c1,c2,c3, a0,a1,a2,a3, b0r,b1r);
        }
        __syncthreads();   // all sAh reads complete before partial overwrite
        float* r0p = sP + ((g*4 + kh)*288) + (m0 + gid)*9 + (tig<<1);
        float* r1p = r0p + 8*9;
        r0p[0] = c0; r0p[1] = c1;
        r1p[0] = c2; r1p[1] = c3;
      }
      __syncthreads();
      if (gh == 0) {
        float l1 = 0.f, l2 = 0.f;
#pragma unroll
        for (int q = 0; q < 4; q++) {
          l1 += sP[q*288     + b_i*9 + d_i];
          l2 += sP[(4+q)*288 + b_i*9 + d_i];
        }
        g_L1[b*Dz + d0 + d_i] = l1;
        g_L2[b*Dz + d0 + d_i] = l2;
      }
    }
    bar_arrive(++bgen);

    // ============ A'(t+1) between arrive and wait ============
    if (t < Tz - 1) {
      epoch_read_lstm(sAh, sWrh, sP, g_embt + (size_t)(t+1)*BD, g_hrt + cur*BD, 0,
                      g_hr + prev*BD, g_hrt + prev*BD,
                      tid, gh, b0, b, d, br, cr_reg);
    }
    bar_wait(bgen);

    // ============ epoch C: fused logits+softmax + write LSTM ============
    {
      // fused: assemble logits in regs, softmax, write fp16 (cols 0..255)
      {
        const int lane = tid & 31, w = tid >> 5;
        const int row = (w << 1) + (lane >> 4);
        const int sub = lane & 15;
        float Sb = g_S[b0 + row];
        float Sc = 1.f - Sb;
        float vals[16]; float mx = -INFINITY;
#pragma unroll
        for (int k = 0; k < 16; k++) {
          int c = sub + (k<<4);
          float o = g_L1[(size_t)(b0+row)*Dz + c]
                  + Sb*g_L2[(size_t)(b0+row)*Dz + c]
                  + Sc*g_wcsum[c] + bc[c];
          vals[k] = o; mx = fmaxf(mx, o);
        }
        mx = fmaxf(mx, __shfl_xor_sync(0xffffffffu, mx, 8));
        mx = fmaxf(mx, __shfl_xor_sync(0xffffffffu, mx, 4));
        mx = fmaxf(mx, __shfl_xor_sync(0xffffffffu, mx, 2));
        mx = fmaxf(mx, __shfl_xor_sync(0xffffffffu, mx, 1));
        float sv = 0.f;
#pragma unroll
        for (int k = 0; k < 16; k++) { vals[k] = __expf(vals[k]-mx); sv += vals[k]; }
        sv += __shfl_xor_sync(0xffffffffu, sv, 8);
        sv += __shfl_xor_sync(0xffffffffu, sv, 4);
        sv += __shfl_xor_sync(0xffffffffu, sv, 2);
        sv += __shfl_xor_sync(0xffffffffu, sv, 1);
        float inv = __fdividef(1.f, sv);
#pragma unroll
        for (int k = 0; k < 16; k++)
          sAh[row*STRH + sub + (k<<4)] = __float2half(vals[k]*inv);
      }
      // stage hw_{t-1} fp16 copy (cols 256..511 = 32 uint4/row)
      {
        const uint4* Hw = (const uint4*)(g_hwt + prev*BD);
        for (int idx = tid; idx < 1024; idx += NT) {
          int r = idx >> 5, c = idx & 31;
          *(uint4*)(sAh + r*STRH + 256 + c*8) = Hw[(size_t)(b0+r)*32 + c];
        }
      }
      __syncthreads();
      float pre[4];
      gemm_lstm_h(sAh, sWwh, sP, tid, pre);
      if (gh == 0) {
        float ig = sigmf(pre[0] + bw[0]);
        float fg = sigmf(pre[1] + bw[1]);
        float gg = tanhff(pre[2] + bw[2]);
        float og = sigmf(pre[3] + bw[3]);
        cw_reg = fmaf(fg, cw_reg, ig*gg);
        float hv = og * tanhff(cw_reg);
        hwc[b*Dz + d] = hv;
        g_hwt[cur*BD + b*Dz + d] = __float2half(hv);
        out[(size_t)t*BD + b*Dz + d] = hv;
      }
    }
    grid_bar(++bgen);   // covers hr_{t+1} (A') and hw_t (C) for B(t+1)/epilogue
  }

  // ================= final: states + M materialization =================
  if (tid < 256) {
    int i = cta*256 + tid;
    out[1048576 + i]         = g_hr[BD + i];   // hr_31 (buffer 1)
    out[1048576 + 65536 + i] = g_hw[BD + i];   // hw_31 (buffer 1)
  }
  if (gh == 0) {
    out[1048576 + 32768 + b*Dz + d] = cr_reg;
    out[1048576 + 98304 + b*Dz + d] = cw_reg;
  }
  {
    if (tid < 256) sHw[tid] = g_hw[BD + bown*Dz + tid];
    __syncthreads();
    const int dq = tid & 63;
    const int lr = tid >> 6;
    float4 hv4 = ((const float4*)sHw)[dq];
    float4 h1;
    h1.x = hv4.x - 1.f; h1.y = hv4.y - 1.f; h1.z = hv4.z - 1.f; h1.w = hv4.w - 1.f;
    float* Mo = out + 1179648 + (size_t)bown*Lz*Dz;
    for (int l = lr; l < Lz; l += 8) {
      float zv = sZ[l];
      float4 o;
      o.x = fmaf(h1.x, zv, 1.f);
      o.y = fmaf(h1.y, zv, 1.f);
      o.z = fmaf(h1.z, zv, 1.f);
      o.w = fmaf(h1.w, zv, 1.f);
      ((float4*)(Mo + (size_t)l*Dz))[dq] = o;
    }
  }
}

// ---------------- zero the barrier flags before each graph replay ----------
__global__ void zero_flags(){
  g_flags[threadIdx.x*32 + blockIdx.x] = 0u;
}

// ---------------- launch ----------------
extern "C" void kernel_launch(void* const* d_in, const int* in_sizes, int n_in,
                              void* d_out, int out_size)
{
  const float* emb   = (const float*)d_in[0];
  const float* hr0   = (const float*)d_in[1];
  const float* cr0   = (const float*)d_in[2];
  const float* hw0   = (const float*)d_in[3];
  const float* cw0   = (const float*)d_in[4];
  const float* M     = (const float*)d_in[5];
  const int*   mask  = (const int*)d_in[6];
  const float* Wih_r = (const float*)d_in[7];
  const float* Whh_r = (const float*)d_in[8];
  const float* bih_r = (const float*)d_in[9];
  const float* bhh_r = (const float*)d_in[10];
  const float* Wc    = (const float*)d_in[11];
  const float* bc    = (const float*)d_in[12];
  const float* Wih_w = (const float*)d_in[13];
  const float* Whh_w = (const float*)d_in[14];
  const float* bih_w = (const float*)d_in[15];
  const float* bhh_w = (const float*)d_in[16];
  float* out = (float*)d_out;

  zero_flags<<<32, NCTA>>>();

  cudaFuncSetAttribute(mega, cudaFuncAttributeMaxDynamicSharedMemorySize, SMEM_BYTES);
  mega<<<NCTA, NT, SMEM_BYTES>>>(emb, hr0, cr0, hw0, cw0, M, mask,
                                 Wih_r, Whh_r, bih_r, bhh_r, Wc, bc,
                                 Wih_w, Whh_w, bih_w, bhh_w, out);
}